// round 1
// baseline (speedup 1.0000x reference)
#include <cuda_runtime.h>

// LinearReg: sum over rows/groups of L2 norm of 25-element groups,
// averaged over rows, scaled by 0.001 * c_omega.
// weight: [N, 800] f32 (N = 100000), 32 groups of 25 per row.

#define GROUPS 32
#define GSIZE 25
#define ROW_ELEMS 800
#define ROWS_PER_BLK 8
#define THREADS 256

__device__ double g_accum;

__global__ void lr_zero_kernel() {
    g_accum = 0.0;
}

__global__ __launch_bounds__(THREADS) void lr_reduce_kernel(
    const float* __restrict__ w, int n)
{
    __shared__ float s[ROWS_PER_BLK * ROW_ELEMS];   // 25.6 KB
    __shared__ float warpsum[THREADS / 32];

    float total = 0.0f;
    int nchunks = (n + ROWS_PER_BLK - 1) / ROWS_PER_BLK;

    for (int chunk = blockIdx.x; chunk < nchunks; chunk += gridDim.x) {
        long long base_row = (long long)chunk * ROWS_PER_BLK;
        int rows = n - (int)base_row;
        if (rows > ROWS_PER_BLK) rows = ROWS_PER_BLK;

        // Coalesced float4 stage of 'rows' contiguous rows into smem.
        const float4* __restrict__ src =
            (const float4*)(w + base_row * ROW_ELEMS);
        float4* s4 = (float4*)s;
        int n4 = rows * ROW_ELEMS / 4;   // ROW_ELEMS % 4 == 0
        #pragma unroll 4
        for (int i = threadIdx.x; i < n4; i += THREADS)
            s4[i] = src[i];
        __syncthreads();

        // warp w -> row w, lane l -> group l. gcd(25,32)=1 => conflict-free.
        int row = threadIdx.x >> 5;
        int grp = threadIdx.x & 31;
        if (row < rows) {
            const float* p = s + row * ROW_ELEMS + grp * GSIZE;
            float acc = 0.0f;
            #pragma unroll
            for (int i = 0; i < GSIZE; i++)
                acc = fmaf(p[i], p[i], acc);
            total += sqrtf(acc);
        }
        __syncthreads();
    }

    // Block reduction of per-thread norm sums.
    #pragma unroll
    for (int o = 16; o > 0; o >>= 1)
        total += __shfl_xor_sync(0xffffffffu, total, o);
    if ((threadIdx.x & 31) == 0)
        warpsum[threadIdx.x >> 5] = total;
    __syncthreads();
    if (threadIdx.x < THREADS / 32) {
        float v = warpsum[threadIdx.x];
        #pragma unroll
        for (int o = (THREADS / 32) / 2; o > 0; o >>= 1)
            v += __shfl_xor_sync(0x000000ffu, v, o);
        if (threadIdx.x == 0)
            atomicAdd(&g_accum, (double)v);
    }
}

__global__ void lr_finalize_kernel(float* out, const unsigned* c_omega_raw, int n)
{
    // c_omega is the python int 1; handle either integer-typed or
    // float32-typed scalar deterministically: a small unsigned value is an
    // integer, a huge bit-pattern (e.g. 0x3F800000) is a float's bits.
    unsigned u = *c_omega_raw;
    float c = (u < (1u << 30)) ? (float)(int)u : __uint_as_float(u);
    out[0] = (float)(g_accum / (double)n * 0.001 * (double)c);
}

extern "C" void kernel_launch(void* const* d_in, const int* in_sizes, int n_in,
                              void* d_out, int out_size)
{
    const float* w = (const float*)d_in[0];
    const unsigned* c_omega = (const unsigned*)d_in[1];
    int n = in_sizes[0] / (GROUPS * GSIZE);   // 100000

    lr_zero_kernel<<<1, 1>>>();

    int nchunks = (n + ROWS_PER_BLK - 1) / ROWS_PER_BLK;
    int blocks = 148 * 8;                      // persistent-ish grid
    if (blocks > nchunks) blocks = nchunks;
    lr_reduce_kernel<<<blocks, THREADS>>>(w, n);

    lr_finalize_kernel<<<1, 1>>>((float*)d_out, c_omega, n);
}

// round 2
// speedup vs baseline: 1.0040x; 1.0040x over previous
#include <cuda_runtime.h>

// LinearReg: sum over rows/groups of L2 norm of 25-element groups,
// averaged over rows, scaled by 0.001 * c_omega.
// weight: [N, 800] f32 (N = 100000), 32 groups of 25 per row.
// Single fused launch: block partials -> decoupled last-block reduction.

#define GROUPS 32
#define GSIZE 25
#define ROW_ELEMS 800
#define ROWS_PER_BLK 8
#define THREADS 256
#define MAXBLOCKS 4096

__device__ float g_partials[MAXBLOCKS];
__device__ unsigned g_count = 0;   // always returns to 0 (last block resets)

__global__ __launch_bounds__(THREADS) void lr_fused_kernel(
    const float* __restrict__ w, const unsigned* __restrict__ c_omega_raw,
    float* __restrict__ out, int n)
{
    __shared__ float s[ROWS_PER_BLK * ROW_ELEMS];   // 25.6 KB
    __shared__ float warpsum[THREADS / 32];
    __shared__ double warpsumd[THREADS / 32];
    __shared__ int is_last;

    float total = 0.0f;
    int nchunks = (n + ROWS_PER_BLK - 1) / ROWS_PER_BLK;

    for (int chunk = blockIdx.x; chunk < nchunks; chunk += gridDim.x) {
        long long base_row = (long long)chunk * ROWS_PER_BLK;
        int rows = n - (int)base_row;
        if (rows > ROWS_PER_BLK) rows = ROWS_PER_BLK;

        // Coalesced float4 stage of 'rows' contiguous rows into smem.
        const float4* __restrict__ src =
            (const float4*)(w + base_row * ROW_ELEMS);
        float4* s4 = (float4*)s;
        int n4 = rows * ROW_ELEMS / 4;   // ROW_ELEMS % 4 == 0
        #pragma unroll 4
        for (int i = threadIdx.x; i < n4; i += THREADS)
            s4[i] = src[i];
        __syncthreads();

        // warp w -> row w, lane l -> group l. gcd(25,32)=1 => conflict-free.
        int row = threadIdx.x >> 5;
        int grp = threadIdx.x & 31;
        if (row < rows) {
            const float* p = s + row * ROW_ELEMS + grp * GSIZE;
            float acc = 0.0f;
            #pragma unroll
            for (int i = 0; i < GSIZE; i++)
                acc = fmaf(p[i], p[i], acc);
            total += sqrtf(acc);
        }
        __syncthreads();
    }

    // Block reduction of per-thread norm sums (float is plenty: <~60 per thread).
    #pragma unroll
    for (int o = 16; o > 0; o >>= 1)
        total += __shfl_xor_sync(0xffffffffu, total, o);
    if ((threadIdx.x & 31) == 0)
        warpsum[threadIdx.x >> 5] = total;
    __syncthreads();

    if (threadIdx.x == 0) {
        float bsum = 0.0f;
        #pragma unroll
        for (int i = 0; i < THREADS / 32; i++)
            bsum += warpsum[i];
        g_partials[blockIdx.x] = bsum;
        __threadfence();                       // publish partial before ticket
        unsigned t = atomicAdd(&g_count, 1u);
        is_last = (t == gridDim.x - 1);
    }
    __syncthreads();

    if (is_last) {
        // Last block: reduce all partials in double, finalize, reset counter.
        double v = 0.0;
        for (int i = threadIdx.x; i < (int)gridDim.x; i += THREADS)
            v += (double)__ldcg(&g_partials[i]);   // bypass L1 (coherence at L2)
        #pragma unroll
        for (int o = 16; o > 0; o >>= 1)
            v += __shfl_xor_sync(0xffffffffu, v, o);
        if ((threadIdx.x & 31) == 0)
            warpsumd[threadIdx.x >> 5] = v;
        __syncthreads();
        if (threadIdx.x == 0) {
            double sum = 0.0;
            #pragma unroll
            for (int i = 0; i < THREADS / 32; i++)
                sum += warpsumd[i];
            // c_omega arrives as python int 1; handle int-typed or f32-typed
            // scalar deterministically by bit pattern magnitude.
            unsigned u = *c_omega_raw;
            float c = (u < (1u << 30)) ? (float)(int)u : __uint_as_float(u);
            out[0] = (float)(sum / (double)n * 0.001 * (double)c);
            g_count = 0;                      // restore for next graph replay
        }
    }
}

extern "C" void kernel_launch(void* const* d_in, const int* in_sizes, int n_in,
                              void* d_out, int out_size)
{
    const float* w = (const float*)d_in[0];
    const unsigned* c_omega = (const unsigned*)d_in[1];
    int n = in_sizes[0] / (GROUPS * GSIZE);   // 100000

    int nchunks = (n + ROWS_PER_BLK - 1) / ROWS_PER_BLK;
    int blocks = 152 * 8;                      // GB300: 152 SMs
    if (blocks > nchunks) blocks = nchunks;
    if (blocks > MAXBLOCKS) blocks = MAXBLOCKS;

    lr_fused_kernel<<<blocks, THREADS>>>(w, c_omega, (float*)d_out, n);
}

// round 3
// speedup vs baseline: 1.0721x; 1.0678x over previous
#include <cuda_runtime.h>
#include <cstdint>

// LinearReg: sum over rows/groups of L2 norm of 25-element groups,
// averaged over rows, scaled by 0.001 * c_omega.
// weight: [N, 800] f32 (N = 100000), 32 groups of 25 per row.
// Single fused launch; cp.async double-buffered staging to overlap
// DRAM fetch with group-norm compute; decoupled last-block reduction.

#define GROUPS 32
#define GSIZE 25
#define ROW_ELEMS 800
#define RPB 8                                   // rows per chunk
#define THREADS 256
#define CHUNK_FLOATS (RPB * ROW_ELEMS)          // 6400
#define CHUNK_VEC (CHUNK_FLOATS / 4)            // 1600 float4
#define SMEM_BYTES (2 * CHUNK_FLOATS * 4)       // 51200 (double buffer)
#define MAXBLOCKS 4096

__device__ float g_partials[MAXBLOCKS];
__device__ unsigned g_count = 0;   // last block resets -> replay-deterministic

__device__ __forceinline__ void cp_async16(uint32_t saddr, const float* gptr) {
    asm volatile("cp.async.cg.shared.global [%0], [%1], 16;\n"
                 :: "r"(saddr), "l"(__cvta_generic_to_global(gptr)));
}
__device__ __forceinline__ void cp_commit() {
    asm volatile("cp.async.commit_group;\n");
}
__device__ __forceinline__ void cp_wait1() {
    asm volatile("cp.async.wait_group 1;\n");
}
__device__ __forceinline__ void cp_wait0() {
    asm volatile("cp.async.wait_group 0;\n");
}

__global__ __launch_bounds__(THREADS) void lr_fused_kernel(
    const float* __restrict__ w, const unsigned* __restrict__ c_omega_raw,
    float* __restrict__ out, int n)
{
    extern __shared__ float s[];                 // [2][CHUNK_FLOATS]
    __shared__ float warpsum[THREADS / 32];
    __shared__ double warpsumd[THREADS / 32];
    __shared__ int is_last;

    const int nchunks = (n + RPB - 1) / RPB;
    const long long total_vec = (long long)n * (ROW_ELEMS / 4);
    const uint32_t sbase = (uint32_t)__cvta_generic_to_shared(s);

    float total = 0.0f;

    // -- prologue: stage first chunk into buffer 0 --
    {
        int c0 = blockIdx.x;
        if (c0 < nchunks) {
            long long gv = (long long)c0 * CHUNK_VEC;
            const float4* src = (const float4*)w;
            #pragma unroll
            for (int i = threadIdx.x; i < CHUNK_VEC; i += THREADS)
                if (gv + i < total_vec)
                    cp_async16(sbase + i * 16, (const float*)&src[gv + i]);
        }
        cp_commit();
    }

    int buf = 0;
    for (int chunk = blockIdx.x; chunk < nchunks; chunk += gridDim.x) {
        // -- issue next chunk into the other buffer --
        int nxt = chunk + gridDim.x;
        bool have_next = (nxt < nchunks);
        if (have_next) {
            long long gv = (long long)nxt * CHUNK_VEC;
            const float4* src = (const float4*)w;
            uint32_t dst = sbase + (buf ^ 1) * (CHUNK_FLOATS * 4);
            #pragma unroll
            for (int i = threadIdx.x; i < CHUNK_VEC; i += THREADS)
                if (gv + i < total_vec)
                    cp_async16(dst + i * 16, (const float*)&src[gv + i]);
        }
        cp_commit();
        if (have_next) cp_wait1(); else cp_wait0();
        __syncthreads();

        // -- compute on current buffer --
        // warp w -> row w, lane l -> group l. gcd(25,32)=1 => conflict-free.
        long long base_row = (long long)chunk * RPB;
        int rows = n - (int)base_row;
        if (rows > RPB) rows = RPB;

        int row = threadIdx.x >> 5;
        int grp = threadIdx.x & 31;
        if (row < rows) {
            const float* p = s + buf * CHUNK_FLOATS + row * ROW_ELEMS + grp * GSIZE;
            float acc = 0.0f;
            #pragma unroll
            for (int i = 0; i < GSIZE; i++)
                acc = fmaf(p[i], p[i], acc);
            total += sqrtf(acc);
        }
        __syncthreads();   // compute done before this buffer is refilled (iter+2)
        buf ^= 1;
    }

    // -- block reduction of per-thread norm sums --
    #pragma unroll
    for (int o = 16; o > 0; o >>= 1)
        total += __shfl_xor_sync(0xffffffffu, total, o);
    if ((threadIdx.x & 31) == 0)
        warpsum[threadIdx.x >> 5] = total;
    __syncthreads();

    if (threadIdx.x == 0) {
        float bsum = 0.0f;
        #pragma unroll
        for (int i = 0; i < THREADS / 32; i++)
            bsum += warpsum[i];
        g_partials[blockIdx.x] = bsum;
        __threadfence();                        // publish partial before ticket
        unsigned t = atomicAdd(&g_count, 1u);
        is_last = (t == gridDim.x - 1);
    }
    __syncthreads();

    if (is_last) {
        double v = 0.0;
        for (int i = threadIdx.x; i < (int)gridDim.x; i += THREADS)
            v += (double)__ldcg(&g_partials[i]);   // bypass L1
        #pragma unroll
        for (int o = 16; o > 0; o >>= 1)
            v += __shfl_xor_sync(0xffffffffu, v, o);
        if ((threadIdx.x & 31) == 0)
            warpsumd[threadIdx.x >> 5] = v;
        __syncthreads();
        if (threadIdx.x == 0) {
            double sum = 0.0;
            #pragma unroll
            for (int i = 0; i < THREADS / 32; i++)
                sum += warpsumd[i];
            // c_omega is the python int 1; accept int-typed or f32-typed
            // scalar deterministically by bit-pattern magnitude.
            unsigned u = *c_omega_raw;
            float c = (u < (1u << 30)) ? (float)(int)u : __uint_as_float(u);
            out[0] = (float)(sum / (double)n * 0.001 * (double)c);
            g_count = 0;                       // restore for next graph replay
        }
    }
}

extern "C" void kernel_launch(void* const* d_in, const int* in_sizes, int n_in,
                              void* d_out, int out_size)
{
    const float* w = (const float*)d_in[0];
    const unsigned* c_omega = (const unsigned*)d_in[1];
    int n = in_sizes[0] / (GROUPS * GSIZE);   // 100000

    cudaFuncSetAttribute(lr_fused_kernel,
                         cudaFuncAttributeMaxDynamicSharedMemorySize, SMEM_BYTES);

    int nchunks = (n + RPB - 1) / RPB;
    int blocks = 152 * 4;                      // 4 blocks/SM (51.2KB smem each)
    if (blocks > nchunks) blocks = nchunks;
    if (blocks > MAXBLOCKS) blocks = MAXBLOCKS;

    lr_fused_kernel<<<blocks, THREADS, SMEM_BYTES>>>(w, c_omega, (float*)d_out, n);
}